// round 11
// baseline (speedup 1.0000x reference)
#include <cuda_runtime.h>

#define NG      512
#define W_IMG   256
#define H_IMG   256
#define NEG_HALF_LOG2E (-0.7213475204444817f)   // -0.5 * log2(e)
#define LOG2EPS (-27.0f)                        // skip if max alpha < 2^-27

__device__ __forceinline__ float ex2_approx(float x) {
    float y; asm("ex2.approx.f32 %0, %1;" : "=f"(y) : "f"(x)); return y;
}
__device__ __forceinline__ float lg2_approx(float x) {
    float y; asm("lg2.approx.f32 %0, %1;" : "=f"(y) : "f"(x)); return y;
}
__device__ __forceinline__ float rcp_approx(float x) {
    float y; asm("rcp.approx.f32 %0, %1;" : "=f"(y) : "f"(x)); return y;
}

// One block = TWO adjacent rows, 512 threads (warps 0-7 -> row 2b, warps
// 8-15 -> row 2b+1). Warps 0-7 prep ONCE for the pair: union row-cull
// (keep0|keep1) + ordered ballot compaction, storing both rows' folded
// terms. Each half runs the 4-group × 64-thread × 4-px second-difference
// mainloop with warp-vote skip; partials combined exactly per row.
// Grid = 128 blocks <= 148 SMs: single wave, no tail imbalance.
__global__ __launch_bounds__(512) void Render_75617194213733_kernel(
    const float* __restrict__ means,    // [NG,2]
    const float* __restrict__ cov,      // [NG,2,2]
    const float* __restrict__ opac,     // [NG]
    const float* __restrict__ colors,   // [NG,3]
    float* __restrict__ out)            // [H,W,3]
{
    __shared__ float4 C0[NG];           // mx, ka, kb*dy0, kd*dy0^2+lop
    __shared__ float4 C1[NG];           // kb*dy1, kd*dy1^2+lop, 2ka, -
    __shared__ float4 C2[NG];           // cr, cg, cb, -
    __shared__ float4 Ppart[2][4][3 * 64];  // [rowHalf][pixel][group-1..3]
    __shared__ int    sCnt[16];
    __shared__ int    sBase[16];
    __shared__ int    sMtot;

    const int tid   = threadIdx.x;
    const int lane  = tid & 31;
    const int warp  = tid >> 5;
    const int half  = tid >> 8;                 // 0 or 1 (which row)
    const int rtid  = tid & 255;
    const int row0  = 2 * blockIdx.x;
    const float py0 = (float)row0 + 0.5f;
    const float py1 = py0 + 1.0f;

    // ── Prep by warps 0-7 only: 2 gaussians/thread, union cull over the pair.
    if (half == 0) {
        float4 A[2], D[2], E[2];
        bool   kp[2];
        unsigned bl[2];
#pragma unroll
        for (int c = 0; c < 2; c++) {
            const int g = rtid + 256 * c;
            float4 cv = ((const float4*)cov)[g];
            float2 mn = ((const float2*)means)[g];
            float  op = opac[g];
            float det = fmaf(cv.x, cv.w, -cv.y * cv.z);
            float s   = NEG_HALF_LOG2E * rcp_approx(det);
            float ka  = s * cv.w;                          // < 0
            float kb  = -s * (cv.y + cv.z);
            float kd  = s * cv.x;                          // < 0
            float lop = lg2_approx(op);
            float q   = kd - kb * kb * rcp_approx(4.0f * ka);
            float dy0 = py0 - mn.y;
            float dy1 = py1 - mn.y;
            bool k0 = fmaf(q, dy0 * dy0, lop) > LOG2EPS;
            bool k1 = fmaf(q, dy1 * dy1, lop) > LOG2EPS;
            kp[c] = k0 || k1;
            bl[c] = __ballot_sync(0xffffffffu, kp[c]);
            if (lane == 0) sCnt[c * 8 + warp] = __popc(bl[c]);
            A[c] = make_float4(mn.x, ka, kb * dy0, fmaf(kd * dy0, dy0, lop));
            D[c] = make_float4(kb * dy1, fmaf(kd * dy1, dy1, lop), ka + ka, 0.f);
            E[c] = make_float4(colors[3 * g + 0], colors[3 * g + 1],
                               colors[3 * g + 2], 0.f);
        }
        __syncthreads();
        // warp-0 shuffle scan of 16 (chunk, warp) counts
        if (warp == 0) {
            int c = (lane < 16) ? sCnt[lane] : 0;
            int inc = c;
#pragma unroll
            for (int d = 1; d < 16; d <<= 1) {
                int n = __shfl_up_sync(0xffffffffu, inc, d);
                if (lane >= d) inc += n;
            }
            if (lane < 16) sBase[lane] = inc - c;
            if (lane == 15) sMtot = inc;
        }
        __syncthreads();
        if (kp[0]) {
            int j = sBase[warp] + __popc(bl[0] & ((1u << lane) - 1u));
            C0[j] = A[0];  C1[j] = D[0];  C2[j] = E[0];
        }
        if (kp[1]) {
            int j = sBase[8 + warp] + __popc(bl[1] & ((1u << lane) - 1u));
            C0[j] = A[1];  C1[j] = D[1];  C2[j] = E[1];
        }
    } else {
        __syncthreads();        // match prep barriers
        __syncthreads();
    }
    __syncthreads();

    const int M     = sMtot;
    const int Mq    = (M + 3) >> 2;
    const int group = (rtid >> 6);      // 0..3 within this row-half
    const int t     = rtid & 63;
    const int j0    = min(group * Mq, M);
    const int j1    = min(j0 + Mq, M);

    const float px = (float)(4 * t) + 0.5f;
    const float py = half ? py1 : py0;

    float T0 = 1.f, T1 = 1.f, T2 = 1.f, T3 = 1.f;
    float r0 = 0.f, g0 = 0.f, b0 = 0.f;
    float r1 = 0.f, g1 = 0.f, b1 = 0.f;
    float r2 = 0.f, g2 = 0.f, b2 = 0.f;
    float r3 = 0.f, g3 = 0.f, b3 = 0.f;

#pragma unroll 2
    for (int j = j0; j < j1; j++) {
        float4 pa = C0[j];              // mx, ka, kbdy0, c1_0
        float4 pd = C1[j];              // kbdy1, c1_1, 2ka, -
        float4 pc = C2[j];              // cr, cg, cb, -
        float kbdy = half ? pd.x : pa.z;            // warp-uniform select
        float c1   = half ? pd.y : pa.w;
        float dx = px - pa.x;
        float t2 = fmaf(pa.y, dx, kbdy);            // ka*dx + kb*dy
        float m0 = fmaf(dx, t2, c1);                // exponent at px
        float s0 = t2 + fmaf(pa.y, dx, pa.y);       // first difference
        float m1 = m0 + s0;
        float s1 = s0 + pd.z;                       // second difference = 2ka
        float m2 = m1 + s1;
        float s2 = s1 + pd.z;
        float m3 = m2 + s2;

        float mm = fmaxf(fmaxf(m0, m1), fmaxf(m2, m3));
        if (__any_sync(0xffffffffu, mm > LOG2EPS)) {
            float a0 = ex2_approx(m0);
            float a1 = ex2_approx(m1);
            float a2 = ex2_approx(m2);
            float a3 = ex2_approx(m3);

            float w0 = a0 * T0, w1 = a1 * T1, w2 = a2 * T2, w3 = a3 * T3;
            r0 = fmaf(w0, pc.x, r0); g0 = fmaf(w0, pc.y, g0); b0 = fmaf(w0, pc.z, b0);
            r1 = fmaf(w1, pc.x, r1); g1 = fmaf(w1, pc.y, g1); b1 = fmaf(w1, pc.z, b1);
            r2 = fmaf(w2, pc.x, r2); g2 = fmaf(w2, pc.y, g2); b2 = fmaf(w2, pc.z, b2);
            r3 = fmaf(w3, pc.x, r3); g3 = fmaf(w3, pc.y, g3); b3 = fmaf(w3, pc.z, b3);
            T0 *= 1.0000001f - a0;          // (1-a)+1e-7, off the critical chain
            T1 *= 1.0000001f - a1;
            T2 *= 1.0000001f - a2;
            T3 *= 1.0000001f - a3;
        }
    }

    // ── Exact segment combine per row-half: C = C_a + T_a * C_b.
    if (group != 0) {
        int pi = (group - 1) * 64 + t;
        Ppart[half][0][pi] = make_float4(r0, g0, b0, T0);
        Ppart[half][1][pi] = make_float4(r1, g1, b1, T1);
        Ppart[half][2][pi] = make_float4(r2, g2, b2, T2);
        Ppart[half][3][pi] = make_float4(r3, g3, b3, T3);
    }
    __syncthreads();
    if (group == 0) {
        float rl[4] = {r0, r1, r2, r3};
        float gl[4] = {g0, g1, g2, g3};
        float bl_[4] = {b0, b1, b2, b3};
        float Tl[4] = {T0, T1, T2, T3};
        float R[4], G[4], B[4];
#pragma unroll
        for (int p = 0; p < 4; p++) {
            float4 q1 = Ppart[half][p][t];
            float4 q2 = Ppart[half][p][64 + t];
            float4 q3 = Ppart[half][p][128 + t];
            float rr = fmaf(q2.w, q3.x, q2.x);
            float gg = fmaf(q2.w, q3.y, q2.y);
            float bb = fmaf(q2.w, q3.z, q2.z);
            rr = fmaf(q1.w, rr, q1.x);
            gg = fmaf(q1.w, gg, q1.y);
            bb = fmaf(q1.w, bb, q1.z);
            R[p] = fmaf(Tl[p], rr, rl[p]);
            G[p] = fmaf(Tl[p], gg, gl[p]);
            B[p] = fmaf(Tl[p], bb, bl_[p]);
        }
        float4* o4 = (float4*)(out + ((row0 + half) * W_IMG + 4 * t) * 3);
        o4[0] = make_float4(R[0], G[0], B[0], R[1]);
        o4[1] = make_float4(G[1], B[1], R[2], G[2]);
        o4[2] = make_float4(B[2], R[3], G[3], B[3]);
    }
}

extern "C" void kernel_launch(void* const* d_in, const int* in_sizes, int n_in,
                              void* d_out, int out_size) {
    const float* means  = nullptr;
    const float* cov    = nullptr;
    const float* opac   = nullptr;
    const float* colors = nullptr;
    for (int i = 0; i < n_in; i++) {
        switch (in_sizes[i]) {
            case NG * 2: means  = (const float*)d_in[i]; break;
            case NG * 4: cov    = (const float*)d_in[i]; break;
            case NG:     opac   = (const float*)d_in[i]; break;
            case NG * 3: colors = (const float*)d_in[i]; break;
            default: break;
        }
    }
    Render_75617194213733_kernel<<<H_IMG / 2, 512>>>(means, cov, opac, colors,
                                                     (float*)d_out);
}

// round 12
// speedup vs baseline: 1.1893x; 1.1893x over previous
#include <cuda_runtime.h>

#define NG      512
#define W_IMG   256
#define H_IMG   256
#define NEG_HALF_LOG2E (-0.7213475204444817f)   // -0.5 * log2(e)
#define LOG2EPS (-27.0f)                        // skip if max alpha < 2^-27

typedef unsigned long long ull;

__device__ __forceinline__ float ex2_approx(float x) {
    float y; asm("ex2.approx.f32 %0, %1;" : "=f"(y) : "f"(x)); return y;
}
__device__ __forceinline__ float lg2_approx(float x) {
    float y; asm("lg2.approx.f32 %0, %1;" : "=f"(y) : "f"(x)); return y;
}
__device__ __forceinline__ float rcp_approx(float x) {
    float y; asm("rcp.approx.f32 %0, %1;" : "=f"(y) : "f"(x)); return y;
}
// Packed f32x2 helpers (FFMA2 path — only reachable via PTX fma.rn.f32x2).
__device__ __forceinline__ ull pk2(float lo, float hi) {
    ull r; asm("mov.b64 %0, {%1, %2};" : "=l"(r) : "f"(lo), "f"(hi)); return r;
}
__device__ __forceinline__ void upk2(ull v, float& lo, float& hi) {
    asm("mov.b64 {%0, %1}, %2;" : "=f"(lo), "=f"(hi) : "l"(v));
}
__device__ __forceinline__ ull mul2(ull a, ull b) {
    ull r; asm("mul.rn.f32x2 %0, %1, %2;" : "=l"(r) : "l"(a), "l"(b)); return r;
}
__device__ __forceinline__ ull fma2(ull a, ull b, ull c) {
    ull r; asm("fma.rn.f32x2 %0, %1, %2, %3;" : "=l"(r) : "l"(a), "l"(b), "l"(c)); return r;
}

// One block per row, 256 threads = 4 groups × 64; each thread composites an
// ordered quarter of the row's survivors for 4 adjacent pixels. Mainloop
// processes 2 gaussians per step (batched LDS for MLP), votes per gaussian,
// and keeps per-pixel-pair (r,g,b,T) state in packed f32x2 registers.
__global__ __launch_bounds__(256) void Render_75617194213733_kernel(
    const float* __restrict__ means,    // [NG,2]
    const float* __restrict__ cov,      // [NG,2,2]
    const float* __restrict__ opac,     // [NG]
    const float* __restrict__ colors,   // [NG,3]
    float* __restrict__ out)            // [H,W,3]
{
    __shared__ float4 C[2 * NG];        // [2j]=(mx,ka,kb*dy,kd*dy^2+lop), [2j+1]=(cr,cg,cb,2ka)
    __shared__ float4 Ppart[4][3 * 64]; // per-pixel partials, groups 1..3
    __shared__ int    sCnt[16];
    __shared__ int    sBase[16];
    __shared__ int    sMtot;

    const int tid  = threadIdx.x;
    const int lane = tid & 31;
    const int warp = tid >> 5;
    const float py = (float)blockIdx.x + 0.5f;

    // ── Fused prep + row cull (2 gaussians/thread).
    float4 A[2], B[2];
    bool   kp[2];
    unsigned bl[2];
#pragma unroll
    for (int c = 0; c < 2; c++) {
        const int g = tid + 256 * c;
        float4 cv = ((const float4*)cov)[g];
        float2 mn = ((const float2*)means)[g];
        float  op = opac[g];
        float det = fmaf(cv.x, cv.w, -cv.y * cv.z);
        float s   = NEG_HALF_LOG2E * rcp_approx(det);
        float ka  = s * cv.w;
        float kb  = -s * (cv.y + cv.z);
        float kd  = s * cv.x;
        float lop = lg2_approx(op);
        float q   = kd - kb * kb * rcp_approx(4.0f * ka);
        float dy  = py - mn.y;
        kp[c] = fmaf(q, dy * dy, lop) > LOG2EPS;
        bl[c] = __ballot_sync(0xffffffffu, kp[c]);
        if (lane == 0) sCnt[c * 8 + warp] = __popc(bl[c]);
        A[c] = make_float4(mn.x, ka, kb * dy, fmaf(kd * dy, dy, lop));
        B[c] = make_float4(colors[3 * g + 0], colors[3 * g + 1],
                           colors[3 * g + 2], ka + ka);
    }
    __syncthreads();

    // ── Warp-0 shuffle scan of the 16 (chunk, warp) counts.
    if (warp == 0) {
        int c = (lane < 16) ? sCnt[lane] : 0;
        int inc = c;
#pragma unroll
        for (int d = 1; d < 16; d <<= 1) {
            int n = __shfl_up_sync(0xffffffffu, inc, d);
            if (lane >= d) inc += n;
        }
        if (lane < 16) sBase[lane] = inc - c;
        if (lane == 15) sMtot = inc;
    }
    __syncthreads();

    const int M = sMtot;
    if (kp[0]) {
        int j = sBase[warp] + __popc(bl[0] & ((1u << lane) - 1u));
        C[2 * j] = A[0];  C[2 * j + 1] = B[0];
    }
    if (kp[1]) {
        int j = sBase[8 + warp] + __popc(bl[1] & ((1u << lane) - 1u));
        C[2 * j] = A[1];  C[2 * j + 1] = B[1];
    }
    __syncthreads();

    const int Mq    = (M + 3) >> 2;
    const int group = tid >> 6;
    const int t     = tid & 63;
    const int j0    = min(group * Mq, M);
    const int j1    = min(j0 + Mq, M);

    const float px = (float)(4 * t) + 0.5f;

    // Packed per-pixel-pair state: P = pixels (0,1), Q = pixels (2,3).
    ull TP = pk2(1.f, 1.f), TQ = pk2(1.f, 1.f);
    ull rP = pk2(0.f, 0.f), gP = rP, bP = rP;
    ull rQ = rP, gQ = rP, bQ = rP;
    const ull NEG1  = pk2(-1.f, -1.f);
    const ull ONEPS = pk2(1.0000001f, 1.0000001f);

    int j = j0;
    for (; j + 1 < j1; j += 2) {
        // Batched loads: 4 × LDS.128 issued before any use.
        float4 paA = C[2 * j],     pbA = C[2 * j + 1];
        float4 paB = C[2 * j + 2], pbB = C[2 * j + 3];

        float dxA = px - paA.x;
        float t2A = fmaf(paA.y, dxA, paA.z);
        float m0A = fmaf(dxA, t2A, paA.w);
        float s0A = t2A + fmaf(paA.y, dxA, paA.y);
        float m1A = m0A + s0A;
        float s1A = s0A + pbA.w;
        float m2A = m1A + s1A;
        float m3A = m2A + s1A + pbA.w;

        float dxB = px - paB.x;
        float t2B = fmaf(paB.y, dxB, paB.z);
        float m0B = fmaf(dxB, t2B, paB.w);
        float s0B = t2B + fmaf(paB.y, dxB, paB.y);
        float m1B = m0B + s0B;
        float s1B = s0B + pbB.w;
        float m2B = m1B + s1B;
        float m3B = m2B + s1B + pbB.w;

        float mmA = fmaxf(fmaxf(m0A, m1A), fmaxf(m2A, m3A));
        float mmB = fmaxf(fmaxf(m0B, m1B), fmaxf(m2B, m3B));

        if (__any_sync(0xffffffffu, mmA > LOG2EPS)) {
            float a0 = ex2_approx(m0A), a1 = ex2_approx(m1A);
            float a2 = ex2_approx(m2A), a3 = ex2_approx(m3A);
            ull aP = pk2(a0, a1), aQ = pk2(a2, a3);
            ull wP = mul2(aP, TP), wQ = mul2(aQ, TQ);
            ull cr2 = pk2(pbA.x, pbA.x);
            ull cg2 = pk2(pbA.y, pbA.y);
            ull cb2 = pk2(pbA.z, pbA.z);
            rP = fma2(wP, cr2, rP); gP = fma2(wP, cg2, gP); bP = fma2(wP, cb2, bP);
            rQ = fma2(wQ, cr2, rQ); gQ = fma2(wQ, cg2, gQ); bQ = fma2(wQ, cb2, bQ);
            TP = mul2(TP, fma2(aP, NEG1, ONEPS));
            TQ = mul2(TQ, fma2(aQ, NEG1, ONEPS));
        }
        if (__any_sync(0xffffffffu, mmB > LOG2EPS)) {
            float a0 = ex2_approx(m0B), a1 = ex2_approx(m1B);
            float a2 = ex2_approx(m2B), a3 = ex2_approx(m3B);
            ull aP = pk2(a0, a1), aQ = pk2(a2, a3);
            ull wP = mul2(aP, TP), wQ = mul2(aQ, TQ);
            ull cr2 = pk2(pbB.x, pbB.x);
            ull cg2 = pk2(pbB.y, pbB.y);
            ull cb2 = pk2(pbB.z, pbB.z);
            rP = fma2(wP, cr2, rP); gP = fma2(wP, cg2, gP); bP = fma2(wP, cb2, bP);
            rQ = fma2(wQ, cr2, rQ); gQ = fma2(wQ, cg2, gQ); bQ = fma2(wQ, cb2, bQ);
            TP = mul2(TP, fma2(aP, NEG1, ONEPS));
            TQ = mul2(TQ, fma2(aQ, NEG1, ONEPS));
        }
    }
    if (j < j1) {       // remainder (uniform across the warp)
        float4 pa = C[2 * j], pb = C[2 * j + 1];
        float dx = px - pa.x;
        float t2 = fmaf(pa.y, dx, pa.z);
        float m0 = fmaf(dx, t2, pa.w);
        float s0 = t2 + fmaf(pa.y, dx, pa.y);
        float m1 = m0 + s0;
        float s1 = s0 + pb.w;
        float m2 = m1 + s1;
        float m3 = m2 + s1 + pb.w;
        float mm = fmaxf(fmaxf(m0, m1), fmaxf(m2, m3));
        if (__any_sync(0xffffffffu, mm > LOG2EPS)) {
            float a0 = ex2_approx(m0), a1 = ex2_approx(m1);
            float a2 = ex2_approx(m2), a3 = ex2_approx(m3);
            ull aP = pk2(a0, a1), aQ = pk2(a2, a3);
            ull wP = mul2(aP, TP), wQ = mul2(aQ, TQ);
            ull cr2 = pk2(pb.x, pb.x);
            ull cg2 = pk2(pb.y, pb.y);
            ull cb2 = pk2(pb.z, pb.z);
            rP = fma2(wP, cr2, rP); gP = fma2(wP, cg2, gP); bP = fma2(wP, cb2, bP);
            rQ = fma2(wQ, cr2, rQ); gQ = fma2(wQ, cg2, gQ); bQ = fma2(wQ, cb2, bQ);
            TP = mul2(TP, fma2(aP, NEG1, ONEPS));
            TQ = mul2(TQ, fma2(aQ, NEG1, ONEPS));
        }
    }

    // Unpack to scalars for the exact combine.
    float r0, r1, r2, r3, g0, g1, g2, g3, b0, b1, b2, b3, T0, T1, T2, T3;
    upk2(rP, r0, r1); upk2(rQ, r2, r3);
    upk2(gP, g0, g1); upk2(gQ, g2, g3);
    upk2(bP, b0, b1); upk2(bQ, b2, b3);
    upk2(TP, T0, T1); upk2(TQ, T2, T3);

    // ── Exact segment combine: C = C_a + T_a * C_b (fold groups 3→2→1→0).
    if (group != 0) {
        int pi = (group - 1) * 64 + t;
        Ppart[0][pi] = make_float4(r0, g0, b0, T0);
        Ppart[1][pi] = make_float4(r1, g1, b1, T1);
        Ppart[2][pi] = make_float4(r2, g2, b2, T2);
        Ppart[3][pi] = make_float4(r3, g3, b3, T3);
    }
    __syncthreads();
    if (group == 0) {
        float rl[4] = {r0, r1, r2, r3};
        float gl[4] = {g0, g1, g2, g3};
        float bl_[4] = {b0, b1, b2, b3};
        float Tl[4] = {T0, T1, T2, T3};
        float R[4], G[4], B[4];
#pragma unroll
        for (int p = 0; p < 4; p++) {
            float4 q1 = Ppart[p][t];
            float4 q2 = Ppart[p][64 + t];
            float4 q3 = Ppart[p][128 + t];
            float rr = fmaf(q2.w, q3.x, q2.x);
            float gg = fmaf(q2.w, q3.y, q2.y);
            float bb = fmaf(q2.w, q3.z, q2.z);
            rr = fmaf(q1.w, rr, q1.x);
            gg = fmaf(q1.w, gg, q1.y);
            bb = fmaf(q1.w, bb, q1.z);
            R[p] = fmaf(Tl[p], rr, rl[p]);
            G[p] = fmaf(Tl[p], gg, gl[p]);
            B[p] = fmaf(Tl[p], bb, bl_[p]);
        }
        float4* o4 = (float4*)(out + (blockIdx.x * W_IMG + 4 * t) * 3);
        o4[0] = make_float4(R[0], G[0], B[0], R[1]);
        o4[1] = make_float4(G[1], B[1], R[2], G[2]);
        o4[2] = make_float4(B[2], R[3], G[3], B[3]);
    }
}

extern "C" void kernel_launch(void* const* d_in, const int* in_sizes, int n_in,
                              void* d_out, int out_size) {
    const float* means  = nullptr;
    const float* cov    = nullptr;
    const float* opac   = nullptr;
    const float* colors = nullptr;
    for (int i = 0; i < n_in; i++) {
        switch (in_sizes[i]) {
            case NG * 2: means  = (const float*)d_in[i]; break;
            case NG * 4: cov    = (const float*)d_in[i]; break;
            case NG:     opac   = (const float*)d_in[i]; break;
            case NG * 3: colors = (const float*)d_in[i]; break;
            default: break;
        }
    }
    Render_75617194213733_kernel<<<H_IMG, 256>>>(means, cov, opac, colors,
                                                 (float*)d_out);
}